// round 11
// baseline (speedup 1.0000x reference)
#include <cuda_runtime.h>

// ---------------------------------------------------------------------------
#define P_ELEMS (96*96*96)          // 884736 points per sample
#define NSAMP   4
#define NB      32
#define NBINS2  (NB*NB)
#define MM_CTAS 74                  // minmax CTAs per sample
#define H_CTAS  74                  // hist CTAs per sample (74*4=296 -> 2/SM)
#define NCOPY   16                  // lane copies per hist CTA (64 KB)

// C = 2048/961 = 2.1311134235 ; exp2 form: C*log2(e)
#define EXP2_C   3.0745468f
#define EXP2_2C  6.1490936f
#define EPS      1e-10f

// ---------------------------------------------------------------------------
// Device scratch (no allocations allowed)
__device__ float    g_pmnT[NSAMP*MM_CTAS];
__device__ float    g_pmxT[NSAMP*MM_CTAS];
__device__ float    g_pmnS[NSAMP*MM_CTAS];
__device__ float    g_pmxS[NSAMP*MM_CTAS];
__device__ float    g_hist[NSAMP*NBINS2];
__device__ unsigned g_tick = 0;     // hist completion ticket

// ---------------------------------------------------------------------------
// Pass 1: per-CTA min/max partials. Batched independent LDG.128 for MLP.
__global__ void __launch_bounds__(1024) k_pre(const float* __restrict__ tar,
                                              const float* __restrict__ src) {
    int b = blockIdx.y;
    if (b == 0) {
        int idx = blockIdx.x * 1024 + threadIdx.x;
        if (idx < NSAMP * NBINS2) g_hist[idx] = 0.0f;
    }

    const float4* t4 = (const float4*)(tar + (size_t)b * P_ELEMS);
    const float4* s4 = (const float4*)(src + (size_t)b * P_ELEMS);
    const int n4 = P_ELEMS / 4;                 // 221184
    const int stride = MM_CTAS * 1024;          // 75776

    const int i = blockIdx.x * 1024 + threadIdx.x;
    float4 a0 = t4[i],          c0 = s4[i];
    float4 a1 = t4[i + stride], c1 = s4[i + stride];

    float mnT = fminf(fminf(fminf(a0.x, a0.y), fminf(a0.z, a0.w)),
                      fminf(fminf(a1.x, a1.y), fminf(a1.z, a1.w)));
    float mxT = fmaxf(fmaxf(fmaxf(a0.x, a0.y), fmaxf(a0.z, a0.w)),
                      fmaxf(fmaxf(a1.x, a1.y), fmaxf(a1.z, a1.w)));
    float mnS = fminf(fminf(fminf(c0.x, c0.y), fminf(c0.z, c0.w)),
                      fminf(fminf(c1.x, c1.y), fminf(c1.z, c1.w)));
    float mxS = fmaxf(fmaxf(fmaxf(c0.x, c0.y), fmaxf(c0.z, c0.w)),
                      fmaxf(fmaxf(c1.x, c1.y), fmaxf(c1.z, c1.w)));

    const int i2 = i + 2 * stride;
    if (i2 < n4) {
        float4 a2 = t4[i2], c2 = s4[i2];
        mnT = fminf(mnT, fminf(fminf(a2.x, a2.y), fminf(a2.z, a2.w)));
        mxT = fmaxf(mxT, fmaxf(fmaxf(a2.x, a2.y), fmaxf(a2.z, a2.w)));
        mnS = fminf(mnS, fminf(fminf(c2.x, c2.y), fminf(c2.z, c2.w)));
        mxS = fmaxf(mxS, fmaxf(fmaxf(c2.x, c2.y), fmaxf(c2.z, c2.w)));
    }

    #pragma unroll
    for (int o = 16; o > 0; o >>= 1) {
        mnT = fminf(mnT, __shfl_xor_sync(0xffffffffu, mnT, o));
        mxT = fmaxf(mxT, __shfl_xor_sync(0xffffffffu, mxT, o));
        mnS = fminf(mnS, __shfl_xor_sync(0xffffffffu, mnS, o));
        mxS = fmaxf(mxS, __shfl_xor_sync(0xffffffffu, mxS, o));
    }
    __shared__ float sm[4][32];
    int w = threadIdx.x >> 5;
    if ((threadIdx.x & 31) == 0) {
        sm[0][w] = mnT; sm[1][w] = mxT; sm[2][w] = mnS; sm[3][w] = mxS;
    }
    __syncthreads();
    if (threadIdx.x == 0) {
        float a = sm[0][0], c = sm[1][0], e = sm[2][0], f = sm[3][0];
        #pragma unroll
        for (int k = 1; k < 32; k++) {
            a = fminf(a, sm[0][k]); c = fmaxf(c, sm[1][k]);
            e = fminf(e, sm[2][k]); f = fmaxf(f, sm[3][k]);
        }
        int slot = b * MM_CTAS + blockIdx.x;
        g_pmnT[slot] = a; g_pmxT[slot] = c;
        g_pmnS[slot] = e; g_pmxS[slot] = f;
    }
}

// ---------------------------------------------------------------------------
// 2-wide Gaussian window, 2 EX2.
// NOTE: f comes from fmaf(t, sc, off) with off rounded separately, so f can be
// a tiny NEGATIVE value at the sample minimum -> MUST clamp below at 0.
__device__ __forceinline__ void gauss2(float f, int& i0, float& w0, float& w1) {
    float i0f = fminf(fmaxf(floorf(f), 0.0f), (float)(NB - 2));
    i0 = (int)i0f;
    float m  = f - i0f;
    float e0 = -EXP2_C * (m * m);
    float e1 = fmaf(EXP2_2C, m, e0 - EXP2_C);   // e0 + C(2m - 1), exp2 domain
    w0 = exp2f(e0);
    w1 = exp2f(e1);
}

// ---------------------------------------------------------------------------
// Pass 2: joint histogram (2x2 window, 4 lane-ATOMS per point) + fused
// last-CTA finalize. 16 lane-copies (64 KB), 2 CTAs/SM, 64 warps/SM.
__global__ void __launch_bounds__(1024, 2) k_hist(const float* __restrict__ tar,
                                                  const float* __restrict__ src,
                                                  float* __restrict__ out) {
    extern __shared__ float sh[];           // [NBINS2][NCOPY] lane-interleaved
    const int b = blockIdx.y;
    const int tid = threadIdx.x;
    const int lane = tid & 31;

    float4* z4 = (float4*)sh;
    #pragma unroll
    for (int i = tid; i < NBINS2 * NCOPY / 4; i += 1024)
        z4[i] = make_float4(0.f, 0.f, 0.f, 0.f);

    __shared__ float lim[4];
    if (tid < 4) {
        const float* arr = (tid == 0) ? g_pmnT : (tid == 1) ? g_pmxT :
                           (tid == 2) ? g_pmnS : g_pmxS;
        bool ismin = (tid & 1) == 0;
        float r = __ldcg(&arr[b * MM_CTAS]);
        #pragma unroll 8
        for (int i = 1; i < MM_CTAS; i++) {
            float v = __ldcg(&arr[b * MM_CTAS + i]);
            r = ismin ? fminf(r, v) : fmaxf(r, v);
        }
        lim[tid] = r;
    }
    __syncthreads();

    // ft = t*scT + offT  (single FFMA per axis)
    const float scT = 31.0f / (lim[1] - lim[0] + 1e-12f);
    const float scS = 31.0f / (lim[3] - lim[2] + 1e-12f);
    const float offT = -lim[0] * scT;
    const float offS = -lim[2] * scS;

    const float4* t4 = (const float4*)(tar + (size_t)b * P_ELEMS);
    const float4* s4 = (const float4*)(src + (size_t)b * P_ELEMS);
    float* hb = sh + (lane & (NCOPY - 1));  // this lane's copy base
    const int n4 = P_ELEMS / 4;

    for (int p = blockIdx.x * 1024 + tid; p < n4; p += H_CTAS * 1024) {
        float4 tv = t4[p];
        float4 sv = s4[p];
        float tf[4] = {tv.x, tv.y, tv.z, tv.w};
        float sf[4] = {sv.x, sv.y, sv.z, sv.w};
        #pragma unroll
        for (int q = 0; q < 4; q++) {
            float ft = fmaf(tf[q], scT, offT);
            float fs = fmaf(sf[q], scS, offS);
            int it0, js0;
            float wt0, wt1, ws0, ws1;
            gauss2(ft, it0, wt0, wt1);
            gauss2(fs, js0, ws0, ws1);

            float* base = hb + ((it0 * NB + js0) << 4);
            atomicAdd(base,                    wt0 * ws0);
            atomicAdd(base + NCOPY,            wt0 * ws1);
            atomicAdd(base + NB * NCOPY,       wt1 * ws0);
            atomicAdd(base + (NB + 1) * NCOPY, wt1 * ws1);
        }
    }

    __syncthreads();
    // merge NCOPY copies per bin (rotated reads), one bin per thread
    {
        const float* c = sh + (tid << 4);
        float s = 0.0f;
        #pragma unroll
        for (int i = 0; i < NCOPY; i++) s += c[(lane + i) & (NCOPY - 1)];
        atomicAdd(&g_hist[b * NBINS2 + tid], s);
    }
    __threadfence();
    __syncthreads();

    // ---- last-CTA finalize (completion ticket, whole-CTA uniform branch) ----
    __shared__ unsigned s_rank;
    if (tid == 0) s_rank = atomicAdd(&g_tick, 1u);
    __syncthreads();

    if (s_rank == H_CTAS * NSAMP - 1) {
        float (*smp)[33] = (float(*)[33])sh;     // reuse smem: [4*32][33]
        __shared__ float part[4];

        if (tid < 128) {
            const int w = tid >> 5, ln = tid & 31;

            float v[32];
            #pragma unroll
            for (int i = 0; i < 32; i++)
                v[i] = __ldcg(&g_hist[w * NBINS2 + i * NB + ln]);  // column 'ln'

            float cs = 0.0f;
            #pragma unroll
            for (int i = 0; i < 32; i++) cs += v[i];
            float norm = cs;
            #pragma unroll
            for (int o = 16; o > 0; o >>= 1)
                norm += __shfl_xor_sync(0xffffffffu, norm, o);
            float inv = __frcp_rn(norm);

            float ej = 0.0f;
            #pragma unroll
            for (int i = 0; i < 32; i++) {
                float p = v[i] * inv;
                smp[w * 32 + i][ln] = p;
                ej += p * __logf(p + EPS);
            }
            #pragma unroll
            for (int o = 16; o > 0; o >>= 1)
                ej += __shfl_xor_sync(0xffffffffu, ej, o);

            float q = cs * inv;
            float es = q * __logf(q + EPS);
            #pragma unroll
            for (int o = 16; o > 0; o >>= 1)
                es += __shfl_xor_sync(0xffffffffu, es, o);

            __syncwarp();
            float r = 0.0f;
            #pragma unroll
            for (int j = 0; j < 32; j++) r += smp[w * 32 + ln][j];
            float et = r * __logf(r + EPS);
            #pragma unroll
            for (int o = 16; o > 0; o >>= 1)
                et += __shfl_xor_sync(0xffffffffu, et, o);

            if (ln == 0) part[w] = (et + es) / ej;
        }
        __syncthreads();     // real block barrier before thread 0 reads part[]
        if (tid == 0) {
            out[0] = -(part[0] + part[1] + part[2] + part[3]) * 0.25f;
            g_tick = 0u;            // reset for next graph replay
        }
    }
}

// ---------------------------------------------------------------------------
extern "C" void kernel_launch(void* const* d_in, const int* in_sizes, int n_in,
                              void* d_out, int out_size) {
    const float* tar = (const float*)d_in[0];
    const float* src = (const float*)d_in[1];
    float* out = (float*)d_out;

    static bool attr_set = false;
    if (!attr_set) {
        cudaFuncSetAttribute(k_hist, cudaFuncAttributeMaxDynamicSharedMemorySize,
                             NBINS2 * NCOPY * sizeof(float));
        attr_set = true;
    }

    k_pre<<<dim3(MM_CTAS, NSAMP), 1024>>>(tar, src);
    k_hist<<<dim3(H_CTAS, NSAMP), 1024, NBINS2 * NCOPY * sizeof(float)>>>(tar, src, out);
}

// round 12
// speedup vs baseline: 1.1714x; 1.1714x over previous
#include <cuda_runtime.h>

// ---------------------------------------------------------------------------
#define P_ELEMS (96*96*96)          // 884736 points per sample
#define NSAMP   4
#define NB      32
#define NBINS2  (NB*NB)
#define MM_CTAS 74                  // minmax CTAs per sample
#define H_CTAS  37                  // hist CTAs per sample (37*4=148, 1/SM)
#define NCOPY   32                  // lane copies per hist CTA (128 KB)
#define HSTRIDE (H_CTAS*1024)       // 37888 float4s

// C = 2048/961 = 2.1311134235 ; exp2 form: C*log2(e)
#define EXP2_C   3.0745468f
#define EXP2_2C  6.1490936f
#define EPS      1e-10f

// ---------------------------------------------------------------------------
// Device scratch (no allocations allowed)
__device__ float    g_pmnT[NSAMP*MM_CTAS];
__device__ float    g_pmxT[NSAMP*MM_CTAS];
__device__ float    g_pmnS[NSAMP*MM_CTAS];
__device__ float    g_pmxS[NSAMP*MM_CTAS];
__device__ float    g_hist[NSAMP*NBINS2];
__device__ unsigned g_tick = 0;     // hist completion ticket

// ---------------------------------------------------------------------------
// Pass 1: per-CTA min/max partials. Batched independent LDG.128 for MLP.
__global__ void __launch_bounds__(1024) k_pre(const float* __restrict__ tar,
                                              const float* __restrict__ src) {
    int b = blockIdx.y;
    if (b == 0) {
        int idx = blockIdx.x * 1024 + threadIdx.x;
        if (idx < NSAMP * NBINS2) g_hist[idx] = 0.0f;
    }

    const float4* t4 = (const float4*)(tar + (size_t)b * P_ELEMS);
    const float4* s4 = (const float4*)(src + (size_t)b * P_ELEMS);
    const int n4 = P_ELEMS / 4;                 // 221184
    const int stride = MM_CTAS * 1024;          // 75776

    const int i = blockIdx.x * 1024 + threadIdx.x;
    float4 a0 = t4[i],          c0 = s4[i];
    float4 a1 = t4[i + stride], c1 = s4[i + stride];

    float mnT = fminf(fminf(fminf(a0.x, a0.y), fminf(a0.z, a0.w)),
                      fminf(fminf(a1.x, a1.y), fminf(a1.z, a1.w)));
    float mxT = fmaxf(fmaxf(fmaxf(a0.x, a0.y), fmaxf(a0.z, a0.w)),
                      fmaxf(fmaxf(a1.x, a1.y), fmaxf(a1.z, a1.w)));
    float mnS = fminf(fminf(fminf(c0.x, c0.y), fminf(c0.z, c0.w)),
                      fminf(fminf(c1.x, c1.y), fminf(c1.z, c1.w)));
    float mxS = fmaxf(fmaxf(fmaxf(c0.x, c0.y), fmaxf(c0.z, c0.w)),
                      fmaxf(fmaxf(c1.x, c1.y), fmaxf(c1.z, c1.w)));

    const int i2 = i + 2 * stride;
    if (i2 < n4) {
        float4 a2 = t4[i2], c2 = s4[i2];
        mnT = fminf(mnT, fminf(fminf(a2.x, a2.y), fminf(a2.z, a2.w)));
        mxT = fmaxf(mxT, fmaxf(fmaxf(a2.x, a2.y), fmaxf(a2.z, a2.w)));
        mnS = fminf(mnS, fminf(fminf(c2.x, c2.y), fminf(c2.z, c2.w)));
        mxS = fmaxf(mxS, fmaxf(fmaxf(c2.x, c2.y), fmaxf(c2.z, c2.w)));
    }

    #pragma unroll
    for (int o = 16; o > 0; o >>= 1) {
        mnT = fminf(mnT, __shfl_xor_sync(0xffffffffu, mnT, o));
        mxT = fmaxf(mxT, __shfl_xor_sync(0xffffffffu, mxT, o));
        mnS = fminf(mnS, __shfl_xor_sync(0xffffffffu, mnS, o));
        mxS = fmaxf(mxS, __shfl_xor_sync(0xffffffffu, mxS, o));
    }
    __shared__ float sm[4][32];
    int w = threadIdx.x >> 5;
    if ((threadIdx.x & 31) == 0) {
        sm[0][w] = mnT; sm[1][w] = mxT; sm[2][w] = mnS; sm[3][w] = mxS;
    }
    __syncthreads();
    if (threadIdx.x == 0) {
        float a = sm[0][0], c = sm[1][0], e = sm[2][0], f = sm[3][0];
        #pragma unroll
        for (int k = 1; k < 32; k++) {
            a = fminf(a, sm[0][k]); c = fmaxf(c, sm[1][k]);
            e = fminf(e, sm[2][k]); f = fmaxf(f, sm[3][k]);
        }
        int slot = b * MM_CTAS + blockIdx.x;
        g_pmnT[slot] = a; g_pmxT[slot] = c;
        g_pmnS[slot] = e; g_pmxS[slot] = f;
    }
}

// ---------------------------------------------------------------------------
// 2-wide Gaussian window, 2 EX2. Lower clamp REQUIRED (f can round < 0).
__device__ __forceinline__ void gauss2(float f, int& i0, float& w0, float& w1) {
    float i0f = fminf(fmaxf(floorf(f), 0.0f), (float)(NB - 2));
    i0 = (int)i0f;
    float m  = f - i0f;
    float e0 = -EXP2_C * (m * m);
    float e1 = fmaf(EXP2_2C, m, e0 - EXP2_C);   // e0 + C(2m - 1), exp2 domain
    w0 = exp2f(e0);
    w1 = exp2f(e1);
}

// Process one float4-pair (4 points) into the lane-interleaved histogram.
__device__ __forceinline__ void hist4(float4 tv, float4 sv,
                                      float scT, float offT,
                                      float scS, float offS,
                                      float* hb) {
    float tf[4] = {tv.x, tv.y, tv.z, tv.w};
    float sf[4] = {sv.x, sv.y, sv.z, sv.w};
    #pragma unroll
    for (int q = 0; q < 4; q++) {
        float ft = fmaf(tf[q], scT, offT);
        float fs = fmaf(sf[q], scS, offS);
        int it0, js0;
        float wt0, wt1, ws0, ws1;
        gauss2(ft, it0, wt0, wt1);
        gauss2(fs, js0, ws0, ws1);

        float* base = hb + ((it0 * NB + js0) << 5);
        atomicAdd(base,                    wt0 * ws0);
        atomicAdd(base + NCOPY,            wt0 * ws1);
        atomicAdd(base + NB * NCOPY,       wt1 * ws0);
        atomicAdd(base + (NB + 1) * NCOPY, wt1 * ws1);
    }
}

// ---------------------------------------------------------------------------
// Pass 2: joint histogram (2x2 window, 4 conflict-free lane-ATOMS per point),
// statically software-pipelined loads (3 rotating buffers, 6 fixed slots),
// + fused last-CTA finalize. 32 lane copies (128 KB), 1 CTA/SM.
__global__ void __launch_bounds__(1024, 1) k_hist(const float* __restrict__ tar,
                                                  const float* __restrict__ src,
                                                  float* __restrict__ out) {
    extern __shared__ float sh[];           // [NBINS2][32] lane-interleaved
    const int b = blockIdx.y;
    const int tid = threadIdx.x;
    const int lane = tid & 31;

    float4* z4 = (float4*)sh;
    #pragma unroll
    for (int i = tid; i < NBINS2 * NCOPY / 4; i += 1024)
        z4[i] = make_float4(0.f, 0.f, 0.f, 0.f);

    __shared__ float lim[4];
    if (tid < 4) {
        const float* arr = (tid == 0) ? g_pmnT : (tid == 1) ? g_pmxT :
                           (tid == 2) ? g_pmnS : g_pmxS;
        bool ismin = (tid & 1) == 0;
        float r = __ldcg(&arr[b * MM_CTAS]);
        #pragma unroll 8
        for (int i = 1; i < MM_CTAS; i++) {
            float v = __ldcg(&arr[b * MM_CTAS + i]);
            r = ismin ? fminf(r, v) : fmaxf(r, v);
        }
        lim[tid] = r;
    }

    // Issue the first 3 load pairs BEFORE the barrier (always in range:
    // base + 2*HSTRIDE <= 37887 + 75776 < 221184).
    const float4* t4 = (const float4*)(tar + (size_t)b * P_ELEMS);
    const float4* s4 = (const float4*)(src + (size_t)b * P_ELEMS);
    const int n4 = P_ELEMS / 4;             // 221184
    const int base = blockIdx.x * 1024 + tid;

    float4 ta0 = t4[base],               sa0 = s4[base];
    float4 ta1 = t4[base + HSTRIDE],     sa1 = s4[base + HSTRIDE];
    float4 ta2 = t4[base + 2 * HSTRIDE], sa2 = s4[base + 2 * HSTRIDE];

    __syncthreads();

    const float scT = 31.0f / (lim[1] - lim[0] + 1e-12f);
    const float scS = 31.0f / (lim[3] - lim[2] + 1e-12f);
    const float offT = -lim[0] * scT;
    const float offS = -lim[2] * scS;

    float* hb = sh + lane;                  // this lane's copy base

    // 6 static slots; iterations 3 & 4 always valid, iteration 5 guarded.
    // (base + 4*HSTRIDE <= 37887 + 151552 < 221184 always; 5*HSTRIDE guarded.)
    const int f5 = base + 5 * HSTRIDE;
    const bool has6 = (f5 < n4);

    // slot 0: process iter0, prefetch iter3
    hist4(ta0, sa0, scT, offT, scS, offS, hb);
    ta0 = t4[base + 3 * HSTRIDE]; sa0 = s4[base + 3 * HSTRIDE];
    // slot 1: process iter1, prefetch iter4
    hist4(ta1, sa1, scT, offT, scS, offS, hb);
    ta1 = t4[base + 4 * HSTRIDE]; sa1 = s4[base + 4 * HSTRIDE];
    // slot 2: process iter2, prefetch iter5 (guarded)
    hist4(ta2, sa2, scT, offT, scS, offS, hb);
    if (has6) { ta2 = t4[f5]; sa2 = s4[f5]; }
    // slots 3..5
    hist4(ta0, sa0, scT, offT, scS, offS, hb);
    hist4(ta1, sa1, scT, offT, scS, offS, hb);
    if (has6) hist4(ta2, sa2, scT, offT, scS, offS, hb);

    __syncthreads();
    // merge NCOPY copies per bin (rotated reads, conflict-free), 1 bin/thread
    {
        const float* c = sh + (tid << 5);
        float s = 0.0f;
        #pragma unroll
        for (int i = 0; i < NCOPY; i++) s += c[(lane + i) & (NCOPY - 1)];
        atomicAdd(&g_hist[b * NBINS2 + tid], s);
    }
    __threadfence();
    __syncthreads();

    // ---- last-CTA finalize (completion ticket, whole-CTA uniform branch) ----
    __shared__ unsigned s_rank;
    if (tid == 0) s_rank = atomicAdd(&g_tick, 1u);
    __syncthreads();

    if (s_rank == H_CTAS * NSAMP - 1) {
        float (*smp)[33] = (float(*)[33])sh;     // reuse smem: [4*32][33]
        __shared__ float part[4];

        if (tid < 128) {
            const int w = tid >> 5, ln = tid & 31;

            float v[32];
            #pragma unroll
            for (int i = 0; i < 32; i++)
                v[i] = __ldcg(&g_hist[w * NBINS2 + i * NB + ln]);  // column 'ln'

            float cs = 0.0f;
            #pragma unroll
            for (int i = 0; i < 32; i++) cs += v[i];
            float norm = cs;
            #pragma unroll
            for (int o = 16; o > 0; o >>= 1)
                norm += __shfl_xor_sync(0xffffffffu, norm, o);
            float inv = __frcp_rn(norm);

            float ej = 0.0f;
            #pragma unroll
            for (int i = 0; i < 32; i++) {
                float p = v[i] * inv;
                smp[w * 32 + i][ln] = p;
                ej += p * __logf(p + EPS);
            }
            #pragma unroll
            for (int o = 16; o > 0; o >>= 1)
                ej += __shfl_xor_sync(0xffffffffu, ej, o);

            float q = cs * inv;
            float es = q * __logf(q + EPS);
            #pragma unroll
            for (int o = 16; o > 0; o >>= 1)
                es += __shfl_xor_sync(0xffffffffu, es, o);

            __syncwarp();
            float r = 0.0f;
            #pragma unroll
            for (int j = 0; j < 32; j++) r += smp[w * 32 + ln][j];
            float et = r * __logf(r + EPS);
            #pragma unroll
            for (int o = 16; o > 0; o >>= 1)
                et += __shfl_xor_sync(0xffffffffu, et, o);

            if (ln == 0) part[w] = (et + es) / ej;
        }
        __syncthreads();     // real block barrier before thread 0 reads part[]
        if (tid == 0) {
            out[0] = -(part[0] + part[1] + part[2] + part[3]) * 0.25f;
            g_tick = 0u;            // reset for next graph replay
        }
    }
}

// ---------------------------------------------------------------------------
extern "C" void kernel_launch(void* const* d_in, const int* in_sizes, int n_in,
                              void* d_out, int out_size) {
    const float* tar = (const float*)d_in[0];
    const float* src = (const float*)d_in[1];
    float* out = (float*)d_out;

    static bool attr_set = false;
    if (!attr_set) {
        cudaFuncSetAttribute(k_hist, cudaFuncAttributeMaxDynamicSharedMemorySize,
                             NBINS2 * NCOPY * sizeof(float));
        attr_set = true;
    }

    k_pre<<<dim3(MM_CTAS, NSAMP), 1024>>>(tar, src);
    k_hist<<<dim3(H_CTAS, NSAMP), 1024, NBINS2 * NCOPY * sizeof(float)>>>(tar, src, out);
}